// round 13
// baseline (speedup 1.0000x reference)
#include <cuda_runtime.h>
#include <cuda_fp16.h>
#include <cuda_bf16.h>

// NGP geodesic-weighted multi-level grid interpolation — fp16 quads, MUFU-free.
//
// Gather side (validated R8-R12): one scattered LDG.128 per level per point
// (fp16 quad of the 2x2x2 corner block), ~4.3 L1 wavefronts/point.
// This round removes the transcendental pipe from the hot loop entirely:
//   * wlon = asin(c*sin(zn))/asin(c*sin(zd)) with zd constant per level
//     -> sn * (1/sd) * (1 + c^2*(sn^2-sd^2)/6), 1/sd & sd^2 baked constants
//     (asin-ratio expansion; residual <= 4e-6 for td <= 0.0698)
//   * c^2 = cos^2(gmin0*r) = 0.5*(1+cos(2theta)) via degree-8 even Taylor
//     (c^2 only scales a <=8e-4 correction -> 1% accuracy is plenty)
//   * per-level cell index = level-0 index >> i (exact: pow2 scaling)
// => zero MUFU (no cos, no div), fewer F2I/FMUL; weight error ~1e-5,
// below the 2.07e-4 fp16 quantization floor.

#define TABLE_SIZE (721 * 1441)

// Reachable quad ranges per level (bl0max*W + bl1max + margin):
#define NQ0 261008
#define NQ1 65712
#define NQ2 16656
#define NQ3 4192
#define QOFF0 0
#define QOFF1 (NQ0)
#define QOFF2 (NQ0 + NQ1)
#define QOFF3 (NQ0 + NQ1 + NQ2)
#define NQUADS (NQ0 + NQ1 + NQ2 + NQ3)

#define BM0 (-90.25f)
#define BM1 (-0.25f)
#define BX0 (90.25f)
#define BX1 (360.25f)
#define RAD 0.017453292519943295f
#define SCALE_UP   8192.0f          // 2^13, exact
#define SCALE_DOWN (1.0f / 8192.0f) // exact

// Per-level wlon denominator constants: zd = gs*RAD/2, sd = zd - zd^3/6.
__device__ __constant__ float INV_SD[4] = {114.593013f, 57.2986883f,
                                           28.6537073f, 14.3355896f};
__device__ __constant__ float SD2[4]    = {7.6152418e-5f, 3.0458649e-4f,
                                           1.2179748e-3f, 4.8659614e-3f};

// fp16 quad: {e00x,e00y,e01x,e01y,e10x,e10y,e11x,e11y} = 16B. Total 5.56 MB.
__device__ __align__(16) __half2 g_quads[4 * NQUADS];

__global__ __launch_bounds__(256)
void build_quads(const float* __restrict__ emb)
{
    int t = blockIdx.x * blockDim.x + threadIdx.x;
    if (t >= NQUADS) return;
    int level, j, W;
    if (t < QOFF1)      { level = 0; j = t;         W = 1440; }
    else if (t < QOFF2) { level = 1; j = t - QOFF1; W = 720;  }
    else if (t < QOFF3) { level = 2; j = t - QOFF2; W = 360;  }
    else                { level = 3; j = t - QOFF3; W = 180;  }
    const float2* tab = reinterpret_cast<const float2*>(emb) + level * TABLE_SIZE;
    float2 a = __ldg(tab + j);        // e00
    float2 b = __ldg(tab + j + 1);    // e01
    float2 c = __ldg(tab + j + W);    // e10
    float2 d = __ldg(tab + j + W + 1);// e11
    __half2* q = &g_quads[4 * t];
    q[0] = __floats2half2_rn(a.x * SCALE_UP, a.y * SCALE_UP);
    q[1] = __floats2half2_rn(b.x * SCALE_UP, b.y * SCALE_UP);
    q[2] = __floats2half2_rn(c.x * SCALE_UP, c.y * SCALE_UP);
    q[3] = __floats2half2_rn(d.x * SCALE_UP, d.y * SCALE_UP);
}

__global__ __launch_bounds__(256, 6)
void interp_kernel(const float* __restrict__ x,
                   float* __restrict__ out,
                   int B)
{
    int b = blockIdx.x * blockDim.x + threadIdx.x;
    if (b >= B) return;

    float2 p  = __ldg(reinterpret_cast<const float2*>(x) + b);
    float lat = p.x, lon = p.y;
    float clat = fminf(fmaxf(lat, BM0), BX0);
    float clon = fminf(fmaxf(lon, BM1), BX1);

    // ---- level-0 cell once; coarser levels by exact pow2 shift ----
    // floor(y * 2^-i) == floor(y) >> i for y >= 0 (2^-i scaling is exact).
    int ib0 = __float2int_rd(clat - BM0);
    int ib1 = __float2int_rd(clon - BM1);

    int bl0a[4], bl1a[4];
#pragma unroll
    for (int i = 0; i < 4; i++) { bl0a[i] = ib0 >> i; bl1a[i] = ib1 >> i; }

    // ---- 4 scattered 128-bit gathers, back-to-back (MLP=4) ----
    const uint4* qt = reinterpret_cast<const uint4*>(g_quads);
    uint4 qa[4];
    qa[0] = __ldg(qt + (QOFF0 + bl0a[0] * 1440 + bl1a[0]));
    qa[1] = __ldg(qt + (QOFF1 + bl0a[1] *  720 + bl1a[1]));
    qa[2] = __ldg(qt + (QOFF2 + bl0a[2] *  360 + bl1a[2]));
    qa[3] = __ldg(qt + (QOFF3 + bl0a[3] *  180 + bl1a[3]));

    // ---- weights (independent of gathers; hides load latency) ----
    float wlat[4], wlon[4];
#pragma unroll
    for (int i = 0; i < 4; i++) {
        const float gs  = (float)(1 << i);
        const float inv = 1.0f / gs;

        float gmin0 = (float)bl0a[i] * gs + BM0;
        float gmin1 = (float)bl1a[i] * gs + BM1;

        // wlat: geodesic along constant lon == |dlat|/gs (UNCLIPPED lat).
        wlat[i] = (lat - gmin0) * inv;

        // sn = sin(zn) (2-term), zn = (gmax1 - lon)*RAD/2 <= 0.0699.
        float dlon = (gmin1 + gs) - lon;
        float zn = dlon * (RAD * 0.5f);
        float sn = zn - zn * zn * zn * (1.0f / 6.0f);

        // c^2 = cos^2(gmin0*RAD) = 0.5*(1 + cos v), v = 2*theta, w = v^2.
        // Degree-8 even Taylor; |v| <= 3.16 -> |err(cos v)| <= 0.03, and c^2
        // only scales a <=8e-4 correction -> wlon error <= ~2.5e-5.
        float th = gmin0 * RAD;
        float w  = 4.0f * th * th;
        float cv = fmaf(w, fmaf(w, fmaf(w, fmaf(w, 1.0f / 40320.0f,
                                               -1.0f / 720.0f),
                                        1.0f / 24.0f),
                                -0.5f), 1.0f);
        float c2 = fmaf(0.5f, cv, 0.5f);

        // wlon = asin(c*sn)/asin(c*sd) ~= sn/sd * (1 + c^2*(sn^2-sd^2)/6).
        float corr = fmaf(c2 * (sn * sn - SD2[i]), 1.0f / 6.0f, 1.0f);
        wlon[i] = sn * INV_SD[i] * corr;
    }

    // ---- consume gathers: bilinear combine ----
    float res[8];
#pragma unroll
    for (int i = 0; i < 4; i++) {
        float2 e00 = __half22float2(*reinterpret_cast<const __half2*>(&qa[i].x));
        float2 e01 = __half22float2(*reinterpret_cast<const __half2*>(&qa[i].y));
        float2 e10 = __half22float2(*reinterpret_cast<const __half2*>(&qa[i].z));
        float2 e11 = __half22float2(*reinterpret_cast<const __half2*>(&qa[i].w));

        float c0x = fmaf(e10.x - e00.x, wlat[i], e00.x);
        float c0y = fmaf(e10.y - e00.y, wlat[i], e00.y);
        float c1x = fmaf(e11.x - e01.x, wlat[i], e01.x);
        float c1y = fmaf(e11.y - e01.y, wlat[i], e01.y);

        res[2 * i + 0] = fmaf(c1x - c0x, wlon[i], c0x) * SCALE_DOWN;
        res[2 * i + 1] = fmaf(c1y - c0y, wlon[i], c0y) * SCALE_DOWN;
    }

    float4* o = reinterpret_cast<float4*>(out) + (size_t)b * 2;
    o[0] = make_float4(res[0], res[1], res[2], res[3]);
    o[1] = make_float4(res[4], res[5], res[6], res[7]);
}

extern "C" void kernel_launch(void* const* d_in, const int* in_sizes, int n_in,
                              void* d_out, int out_size)
{
    const float* x   = (const float*)d_in[0];
    const float* emb = (const float*)d_in[1];
    float*       out = (float*)d_out;

    int B = in_sizes[0] / 2;
    const int T = 256;

    build_quads<<<(NQUADS + T - 1) / T, T>>>(emb);
    interp_kernel<<<(B + T - 1) / T, T>>>(x, out, B);
}

// round 14
// speedup vs baseline: 1.0117x; 1.0117x over previous
#include <cuda_runtime.h>
#include <cuda_fp16.h>
#include <cuda_bf16.h>

// NGP geodesic-weighted multi-level grid interpolation — single 64B record.
//
// Structural insight: level-i cell = level-0 cell >> i, so ONE table indexed
// by the level-0 cell holds all four levels' fp16 corner-quads:
//   rec[cell0] = {quad_L0, quad_L1, quad_L2, quad_L3}   (64B, 64B-aligned)
// Per point the 4 scattered LDG.128 (4 distinct 128B lines) become TWO
// LDG.256 to the SAME 128B line. Calibrated costs (R8/R9): LDG.128 scattered
// = 1.0 wf-unit, LDG.256 = 1.63 -> ~3.8 wf/pt vs 4.55, plus upside from
// same-line pairing. Table 261008 x 64B = 16.7MB, L2-resident.
// Weight math is the validated MUFU-free version (R13), rel_err 2.07e-4.

#define TABLE_SIZE (721 * 1441)

#define NREC 261008   // >= 180*1440 + 360 + margin (reachable level-0 cells)

#define BM0 (-90.25f)
#define BM1 (-0.25f)
#define BX0 (90.25f)
#define BX1 (360.25f)
#define RAD 0.017453292519943295f
#define SCALE_UP   8192.0f          // 2^13, exact
#define SCALE_DOWN (1.0f / 8192.0f) // exact

// Per-level wlon denominator constants: zd = gs*RAD/2, sd = zd - zd^3/6.
__device__ __constant__ float INV_SD[4] = {114.593013f, 57.2986883f,
                                           28.6537073f, 14.3355896f};
__device__ __constant__ float SD2[4]    = {7.6152418e-5f, 3.0458649e-4f,
                                           1.2179748e-3f, 4.8659614e-3f};

// rec[cell0] = 4 x fp16-quad {e00x,e00y,e01x,e01y,e10x,e10y,e11x,e11y}.
__device__ __align__(64) uint4 g_recs[4 * NREC];   // 16.7 MB

// 4 threads per record, one per level -> fully coalesced 16B stores.
__global__ __launch_bounds__(256)
void build_recs(const float* __restrict__ emb)
{
    int t = blockIdx.x * blockDim.x + threadIdx.x;
    if (t >= 4 * NREC) return;
    int rec = t >> 2;
    int lvl = t & 3;

    int ib0 = rec / 1440;
    int ib1 = rec - ib0 * 1440;

    int W = 1440 >> lvl;
    int j = (ib0 >> lvl) * W + (ib1 >> lvl);

    const float2* tab = reinterpret_cast<const float2*>(emb) + lvl * TABLE_SIZE;
    float2 a = __ldg(tab + j);         // e00
    float2 b = __ldg(tab + j + 1);     // e01
    float2 c = __ldg(tab + j + W);     // e10
    float2 d = __ldg(tab + j + W + 1); // e11

    __half2 h0 = __floats2half2_rn(a.x * SCALE_UP, a.y * SCALE_UP);
    __half2 h1 = __floats2half2_rn(b.x * SCALE_UP, b.y * SCALE_UP);
    __half2 h2 = __floats2half2_rn(c.x * SCALE_UP, c.y * SCALE_UP);
    __half2 h3 = __floats2half2_rn(d.x * SCALE_UP, d.y * SCALE_UP);

    uint4 q;
    q.x = *reinterpret_cast<unsigned*>(&h0);
    q.y = *reinterpret_cast<unsigned*>(&h1);
    q.z = *reinterpret_cast<unsigned*>(&h2);
    q.w = *reinterpret_cast<unsigned*>(&h3);
    g_recs[t] = q;
}

// 256-bit global load (Blackwell LDG.E.256); bits only, via f32 regs.
__device__ __forceinline__ void ldg256(const uint4* p, uint4& a, uint4& b)
{
    float ax, ay, az, aw, bx, by, bz, bw;
    asm volatile("ld.global.v8.f32 {%0,%1,%2,%3,%4,%5,%6,%7}, [%8];"
                 : "=f"(ax), "=f"(ay), "=f"(az), "=f"(aw),
                   "=f"(bx), "=f"(by), "=f"(bz), "=f"(bw)
                 : "l"(p));
    a.x = __float_as_uint(ax); a.y = __float_as_uint(ay);
    a.z = __float_as_uint(az); a.w = __float_as_uint(aw);
    b.x = __float_as_uint(bx); b.y = __float_as_uint(by);
    b.z = __float_as_uint(bz); b.w = __float_as_uint(bw);
}

__global__ __launch_bounds__(256, 6)
void interp_kernel(const float* __restrict__ x,
                   float* __restrict__ out,
                   int B)
{
    int b = blockIdx.x * blockDim.x + threadIdx.x;
    if (b >= B) return;

    float2 p  = __ldg(reinterpret_cast<const float2*>(x) + b);
    float lat = p.x, lon = p.y;
    float clat = fminf(fmaxf(lat, BM0), BX0);
    float clon = fminf(fmaxf(lon, BM1), BX1);

    // Level-0 cell; coarser levels by exact pow2 shift.
    int ib0 = __float2int_rd(clat - BM0);
    int ib1 = __float2int_rd(clon - BM1);

    // ONE record: two LDG.256 to the same 128B line.
    const uint4* rec = g_recs + (size_t)(ib0 * 1440 + ib1) * 4;
    uint4 qa[4];
    ldg256(rec,     qa[0], qa[1]);
    ldg256(rec + 2, qa[2], qa[3]);

    // ---- weights (independent of gathers; hides load latency) ----
    float wlat[4], wlon[4];
#pragma unroll
    for (int i = 0; i < 4; i++) {
        const float gs  = (float)(1 << i);
        const float inv = 1.0f / gs;

        float gmin0 = (float)(ib0 >> i) * gs + BM0;
        float gmin1 = (float)(ib1 >> i) * gs + BM1;

        // wlat: geodesic along constant lon == |dlat|/gs (UNCLIPPED lat).
        wlat[i] = (lat - gmin0) * inv;

        // sn = sin(zn) (2-term), zn = (gmax1 - lon)*RAD/2 <= 0.0699.
        float dlon = (gmin1 + gs) - lon;
        float zn = dlon * (RAD * 0.5f);
        float sn = zn - zn * zn * zn * (1.0f / 6.0f);

        // c^2 = cos^2(gmin0*RAD) via degree-8 even Taylor of cos(2theta);
        // c^2 only scales a <=8e-4 correction -> error <= ~2.5e-5 in wlon.
        float th = gmin0 * RAD;
        float w  = 4.0f * th * th;
        float cv = fmaf(w, fmaf(w, fmaf(w, fmaf(w, 1.0f / 40320.0f,
                                               -1.0f / 720.0f),
                                        1.0f / 24.0f),
                                -0.5f), 1.0f);
        float c2 = fmaf(0.5f, cv, 0.5f);

        // wlon = asin(c*sn)/asin(c*sd) ~= sn/sd * (1 + c^2*(sn^2-sd^2)/6).
        float corr = fmaf(c2 * (sn * sn - SD2[i]), 1.0f / 6.0f, 1.0f);
        wlon[i] = sn * INV_SD[i] * corr;
    }

    // ---- consume gathers: bilinear combine ----
    float res[8];
#pragma unroll
    for (int i = 0; i < 4; i++) {
        float2 e00 = __half22float2(*reinterpret_cast<const __half2*>(&qa[i].x));
        float2 e01 = __half22float2(*reinterpret_cast<const __half2*>(&qa[i].y));
        float2 e10 = __half22float2(*reinterpret_cast<const __half2*>(&qa[i].z));
        float2 e11 = __half22float2(*reinterpret_cast<const __half2*>(&qa[i].w));

        float c0x = fmaf(e10.x - e00.x, wlat[i], e00.x);
        float c0y = fmaf(e10.y - e00.y, wlat[i], e00.y);
        float c1x = fmaf(e11.x - e01.x, wlat[i], e01.x);
        float c1y = fmaf(e11.y - e01.y, wlat[i], e01.y);

        res[2 * i + 0] = fmaf(c1x - c0x, wlon[i], c0x) * SCALE_DOWN;
        res[2 * i + 1] = fmaf(c1y - c0y, wlon[i], c0y) * SCALE_DOWN;
    }

    float4* o = reinterpret_cast<float4*>(out) + (size_t)b * 2;
    o[0] = make_float4(res[0], res[1], res[2], res[3]);
    o[1] = make_float4(res[4], res[5], res[6], res[7]);
}

extern "C" void kernel_launch(void* const* d_in, const int* in_sizes, int n_in,
                              void* d_out, int out_size)
{
    const float* x   = (const float*)d_in[0];
    const float* emb = (const float*)d_in[1];
    float*       out = (float*)d_out;

    int B = in_sizes[0] / 2;
    const int T = 256;

    build_recs<<<(4 * NREC + T - 1) / T, T>>>(emb);
    interp_kernel<<<(B + T - 1) / T, T>>>(x, out, B);
}

// round 15
// speedup vs baseline: 1.2035x; 1.1896x over previous
#include <cuda_runtime.h>
#include <cuda_fp16.h>
#include <cuda_bf16.h>

// NGP geodesic-weighted multi-level grid interpolation — 64B fused record,
// lane-pair split: 2 threads per point, one LDG.256 each, no data exchange.
//
// Record table (R14, validated): rec[cell0] = 4 fp16 corner-quads (one per
// level, level-i cell = cell0 >> i), 64B aligned, 16.7MB, L2-resident.
// This round: thread t = (point t>>1, half t&1). Each lane loads 32B
// (its two levels) with ONE LDG.256; lane pairs hit the SAME 128B line so
// L1 merges them within the instruction -> ~half the gather wavefronts.
// Each lane computes only its two levels' weights and stores its own
// contiguous float4 of the output row. No shuffles needed anywhere.

#define TABLE_SIZE (721 * 1441)

#define NREC 261008   // >= 180*1440 + 360 + margin (reachable level-0 cells)

#define BM0 (-90.25f)
#define BM1 (-0.25f)
#define BX0 (90.25f)
#define BX1 (360.25f)
#define RAD 0.017453292519943295f
#define SCALE_UP   8192.0f          // 2^13, exact
#define SCALE_DOWN (1.0f / 8192.0f) // exact

// Per-level wlon denominator constants: zd = gs*RAD/2, sd = zd - zd^3/6.
__device__ __constant__ float INV_SD[4] = {114.593013f, 57.2986883f,
                                           28.6537073f, 14.3355896f};
__device__ __constant__ float SD2[4]    = {7.6152418e-5f, 3.0458649e-4f,
                                           1.2179748e-3f, 4.8659614e-3f};

// rec[cell0] = 4 x fp16-quad {e00x,e00y,e01x,e01y,e10x,e10y,e11x,e11y}.
__device__ __align__(64) uint4 g_recs[4 * NREC];   // 16.7 MB

// 4 threads per record, one per level -> fully coalesced 16B stores.
__global__ __launch_bounds__(256)
void build_recs(const float* __restrict__ emb)
{
    int t = blockIdx.x * blockDim.x + threadIdx.x;
    if (t >= 4 * NREC) return;
    int rec = t >> 2;
    int lvl = t & 3;

    int ib0 = rec / 1440;
    int ib1 = rec - ib0 * 1440;

    int W = 1440 >> lvl;
    int j = (ib0 >> lvl) * W + (ib1 >> lvl);

    const float2* tab = reinterpret_cast<const float2*>(emb) + lvl * TABLE_SIZE;
    float2 a = __ldg(tab + j);         // e00
    float2 b = __ldg(tab + j + 1);     // e01
    float2 c = __ldg(tab + j + W);     // e10
    float2 d = __ldg(tab + j + W + 1); // e11

    __half2 h0 = __floats2half2_rn(a.x * SCALE_UP, a.y * SCALE_UP);
    __half2 h1 = __floats2half2_rn(b.x * SCALE_UP, b.y * SCALE_UP);
    __half2 h2 = __floats2half2_rn(c.x * SCALE_UP, c.y * SCALE_UP);
    __half2 h3 = __floats2half2_rn(d.x * SCALE_UP, d.y * SCALE_UP);

    uint4 q;
    q.x = *reinterpret_cast<unsigned*>(&h0);
    q.y = *reinterpret_cast<unsigned*>(&h1);
    q.z = *reinterpret_cast<unsigned*>(&h2);
    q.w = *reinterpret_cast<unsigned*>(&h3);
    g_recs[t] = q;
}

// 256-bit global load (Blackwell LDG.E.256); bits only, via f32 regs.
__device__ __forceinline__ void ldg256(const uint4* p, uint4& a, uint4& b)
{
    float ax, ay, az, aw, bx, by, bz, bw;
    asm volatile("ld.global.v8.f32 {%0,%1,%2,%3,%4,%5,%6,%7}, [%8];"
                 : "=f"(ax), "=f"(ay), "=f"(az), "=f"(aw),
                   "=f"(bx), "=f"(by), "=f"(bz), "=f"(bw)
                 : "l"(p));
    a.x = __float_as_uint(ax); a.y = __float_as_uint(ay);
    a.z = __float_as_uint(az); a.w = __float_as_uint(aw);
    b.x = __float_as_uint(bx); b.y = __float_as_uint(by);
    b.z = __float_as_uint(bz); b.w = __float_as_uint(bw);
}

__global__ __launch_bounds__(256, 6)
void interp_kernel(const float* __restrict__ x,
                   float* __restrict__ out,
                   int B)
{
    int t  = blockIdx.x * blockDim.x + threadIdx.x;
    int pt = t >> 1;            // point index
    int h  = t & 1;             // half: levels {2h, 2h+1}
    if (pt >= B) return;

    float2 p  = __ldg(reinterpret_cast<const float2*>(x) + pt);
    float lat = p.x, lon = p.y;
    float clat = fminf(fmaxf(lat, BM0), BX0);
    float clon = fminf(fmaxf(lon, BM1), BX1);

    // Level-0 cell; coarser levels by exact pow2 shift.
    int ib0 = __float2int_rd(clat - BM0);
    int ib1 = __float2int_rd(clon - BM1);

    // ONE LDG.256: this lane's 32B half of the 64B record.
    // Lane pairs hit the same 128B line -> merged wavefront.
    const uint4* rec = g_recs + ((size_t)(ib0 * 1440 + ib1) * 4 + h * 2);
    uint4 qa[2];
    ldg256(rec, qa[0], qa[1]);

    // ---- two levels per lane: weights then bilinear ----
    float res[4];
#pragma unroll
    for (int k = 0; k < 2; k++) {
        const int   lvl = 2 * h + k;
        const float gs  = (float)(1 << lvl);
        const float inv = 1.0f / gs;

        float gmin0 = (float)(ib0 >> lvl) * gs + BM0;
        float gmin1 = (float)(ib1 >> lvl) * gs + BM1;

        // wlat: geodesic along constant lon == |dlat|/gs (UNCLIPPED lat).
        float wlat = (lat - gmin0) * inv;

        // sn = sin(zn) (2-term), zn = (gmax1 - lon)*RAD/2 <= 0.0699.
        float dlon = (gmin1 + gs) - lon;
        float zn = dlon * (RAD * 0.5f);
        float sn = zn - zn * zn * zn * (1.0f / 6.0f);

        // c^2 = cos^2(gmin0*RAD) via degree-8 even Taylor of cos(2theta);
        // c^2 only scales a <=8e-4 correction -> error <= ~2.5e-5 in wlon.
        float th = gmin0 * RAD;
        float w  = 4.0f * th * th;
        float cv = fmaf(w, fmaf(w, fmaf(w, fmaf(w, 1.0f / 40320.0f,
                                               -1.0f / 720.0f),
                                        1.0f / 24.0f),
                                -0.5f), 1.0f);
        float c2 = fmaf(0.5f, cv, 0.5f);

        // wlon = asin(c*sn)/asin(c*sd) ~= sn/sd * (1 + c^2*(sn^2-sd^2)/6).
        float corr = fmaf(c2 * (sn * sn - SD2[lvl]), 1.0f / 6.0f, 1.0f);
        float wlon = sn * INV_SD[lvl] * corr;

        float2 e00 = __half22float2(*reinterpret_cast<const __half2*>(&qa[k].x));
        float2 e01 = __half22float2(*reinterpret_cast<const __half2*>(&qa[k].y));
        float2 e10 = __half22float2(*reinterpret_cast<const __half2*>(&qa[k].z));
        float2 e11 = __half22float2(*reinterpret_cast<const __half2*>(&qa[k].w));

        float c0x = fmaf(e10.x - e00.x, wlat, e00.x);
        float c0y = fmaf(e10.y - e00.y, wlat, e00.y);
        float c1x = fmaf(e11.x - e01.x, wlat, e01.x);
        float c1y = fmaf(e11.y - e01.y, wlat, e01.y);

        res[2 * k + 0] = fmaf(c1x - c0x, wlon, c0x) * SCALE_DOWN;
        res[2 * k + 1] = fmaf(c1y - c0y, wlon, c0y) * SCALE_DOWN;
    }

    // Each lane stores its own 16B of the 32B output row (coalesced).
    reinterpret_cast<float4*>(out)[(size_t)pt * 2 + h] =
        make_float4(res[0], res[1], res[2], res[3]);
}

extern "C" void kernel_launch(void* const* d_in, const int* in_sizes, int n_in,
                              void* d_out, int out_size)
{
    const float* x   = (const float*)d_in[0];
    const float* emb = (const float*)d_in[1];
    float*       out = (float*)d_out;

    int B = in_sizes[0] / 2;
    const int T = 256;

    build_recs<<<(4 * NREC + T - 1) / T, T>>>(emb);

    long long nthreads = 2LL * B;
    interp_kernel<<<(int)((nthreads + T - 1) / T), T>>>(x, out, B);
}

// round 16
// speedup vs baseline: 1.3147x; 1.0924x over previous
#include <cuda_runtime.h>
#include <cuda_fp16.h>
#include <cuda_bf16.h>

// NGP geodesic-weighted multi-level grid interpolation — 64B fused record,
// lane-pair split (R15), instruction-diet round: fp16 first-stage lerp,
// once-per-lane cos^2, algebraic index/weight folds.
//
// R15 profile: L1 48.9%, issue 69.2% -> issue-bound. This round removes
// ~30% of the per-lane instruction stream:
//  * lat-lerp done in fp16 (HSUB2/HFMA2) on the stored half2 corners; only
//    c0/c1 are converted to fp32 (saves ~7 instr/level). Adds ~1-2e-4 RMS
//    error on top of the 2.07e-4 fp16 storage floor (tol 1e-3).
//  * c^2 = cos^2(lat) computed ONCE per lane from clat (it only scales a
//    <=8e-4 correction term; shift <= gs*RAD -> wlon err <= 1.1e-4).
//  * wlat = fma(lat-BM0, inv, -fi0); zn = fma(K_l, fi1+1, -lonr);
//    sn^2 ~ zn^2 in the asin correction (err 1.3e-6).

#define TABLE_SIZE (721 * 1441)

#define NREC 261008   // >= 180*1440 + 360 + margin (reachable level-0 cells)

#define BM0 (-90.25f)
#define BM1 (-0.25f)
#define BX0 (90.25f)
#define BX1 (360.25f)
#define RAD 0.017453292519943295f
#define SCALE_UP   8192.0f          // 2^13, exact
#define SCALE_DOWN (1.0f / 8192.0f) // exact

// Per-level constants: K = gs*RAD/2; sd = zd - zd^3/6 (zd = K); 1/sd; sd^2.
__device__ __constant__ float KH[4]     = {0.0087266462f, 0.0174532925f,
                                           0.0349065850f, 0.0698131701f};
__device__ __constant__ float INV_SD[4] = {114.593013f, 57.2986883f,
                                           28.6537073f, 14.3355896f};
__device__ __constant__ float SD2[4]    = {7.6152418e-5f, 3.0458649e-4f,
                                           1.2179748e-3f, 4.8659614e-3f};

// rec[cell0] = 4 x fp16-quad {e00x,e00y,e01x,e01y,e10x,e10y,e11x,e11y}.
__device__ __align__(64) uint4 g_recs[4 * NREC];   // 16.7 MB

// 4 threads per record, one per level -> fully coalesced 16B stores.
__global__ __launch_bounds__(256)
void build_recs(const float* __restrict__ emb)
{
    int t = blockIdx.x * blockDim.x + threadIdx.x;
    if (t >= 4 * NREC) return;
    int rec = t >> 2;
    int lvl = t & 3;

    int ib0 = rec / 1440;
    int ib1 = rec - ib0 * 1440;

    int W = 1440 >> lvl;
    int j = (ib0 >> lvl) * W + (ib1 >> lvl);

    const float2* tab = reinterpret_cast<const float2*>(emb) + lvl * TABLE_SIZE;
    float2 a = __ldg(tab + j);         // e00
    float2 b = __ldg(tab + j + 1);     // e01
    float2 c = __ldg(tab + j + W);     // e10
    float2 d = __ldg(tab + j + W + 1); // e11

    __half2 h0 = __floats2half2_rn(a.x * SCALE_UP, a.y * SCALE_UP);
    __half2 h1 = __floats2half2_rn(b.x * SCALE_UP, b.y * SCALE_UP);
    __half2 h2 = __floats2half2_rn(c.x * SCALE_UP, c.y * SCALE_UP);
    __half2 h3 = __floats2half2_rn(d.x * SCALE_UP, d.y * SCALE_UP);

    uint4 q;
    q.x = *reinterpret_cast<unsigned*>(&h0);
    q.y = *reinterpret_cast<unsigned*>(&h1);
    q.z = *reinterpret_cast<unsigned*>(&h2);
    q.w = *reinterpret_cast<unsigned*>(&h3);
    g_recs[t] = q;
}

// 256-bit global load (Blackwell LDG.E.256); bits only, via f32 regs.
__device__ __forceinline__ void ldg256(const uint4* p, uint4& a, uint4& b)
{
    float ax, ay, az, aw, bx, by, bz, bw;
    asm volatile("ld.global.v8.f32 {%0,%1,%2,%3,%4,%5,%6,%7}, [%8];"
                 : "=f"(ax), "=f"(ay), "=f"(az), "=f"(aw),
                   "=f"(bx), "=f"(by), "=f"(bz), "=f"(bw)
                 : "l"(p));
    a.x = __float_as_uint(ax); a.y = __float_as_uint(ay);
    a.z = __float_as_uint(az); a.w = __float_as_uint(aw);
    b.x = __float_as_uint(bx); b.y = __float_as_uint(by);
    b.z = __float_as_uint(bz); b.w = __float_as_uint(bw);
}

__global__ __launch_bounds__(256, 6)
void interp_kernel(const float* __restrict__ x,
                   float* __restrict__ out,
                   int B)
{
    int t  = blockIdx.x * blockDim.x + threadIdx.x;
    int pt = t >> 1;            // point index
    int h  = t & 1;             // half: levels {2h, 2h+1}
    if (pt >= B) return;

    float2 p  = __ldg(reinterpret_cast<const float2*>(x) + pt);
    float lat = p.x, lon = p.y;
    float clat = fminf(fmaxf(lat, BM0), BX0);
    float clon = fminf(fmaxf(lon, BM1), BX1);

    // Level-0 cell; coarser levels by exact pow2 shift.
    int ib0 = __float2int_rd(clat - BM0);
    int ib1 = __float2int_rd(clon - BM1);

    // ONE LDG.256: this lane's 32B half of the 64B record (lane pairs share
    // the 128B line -> merged wavefront).
    const uint4* rec = g_recs + ((size_t)(ib0 * 1440 + ib1) * 4 + h * 2);
    uint4 qa[2];
    ldg256(rec, qa[0], qa[1]);

    // Per-lane shared terms.
    float latb = lat - BM0;                 // wlat uses UNCLIPPED lat
    float lonr = (lon - BM1) * (RAD * 0.5f);

    // c^2 = cos^2(clat*RAD) via degree-8 even Taylor of cos(2theta), once.
    float th = clat * RAD;
    float w  = 4.0f * th * th;
    float cv = fmaf(w, fmaf(w, fmaf(w, fmaf(w, 1.0f / 40320.0f,
                                           -1.0f / 720.0f),
                                    1.0f / 24.0f),
                            -0.5f), 1.0f);
    float c2_6 = fmaf(0.5f, cv, 0.5f) * (1.0f / 6.0f);

    float res[4];
#pragma unroll
    for (int k = 0; k < 2; k++) {
        const int   lvl = 2 * h + k;
        const float inv = 1.0f / (float)(1 << lvl);

        float fi0  = (float)(ib0 >> lvl);
        float fi1p = (float)((ib1 >> lvl) + 1);

        // wlat = (lat - gmin0)/gs = (lat-BM0)*inv - fi0.
        float wlat = fmaf(latb, inv, -fi0);

        // zn = (gmax1 - lon)*RAD/2 = K*fi1p - lonr;  sn = sin(zn) (2-term).
        float zn  = fmaf(KH[lvl], fi1p, -lonr);
        float zn2 = zn * zn;
        float sn  = zn * fmaf(zn2, -1.0f / 6.0f, 1.0f);

        // wlon = asin(c*sn)/asin(c*sd) ~= sn/sd * (1 + c^2*(zn^2-sd^2)/6).
        float wlon = sn * INV_SD[lvl] * fmaf(c2_6, zn2 - SD2[lvl], 1.0f);

        // fp16 lat-lerp on stored half2 corners; fp32 lon-lerp.
        const __half2 e00 = *reinterpret_cast<const __half2*>(&qa[k].x);
        const __half2 e01 = *reinterpret_cast<const __half2*>(&qa[k].y);
        const __half2 e10 = *reinterpret_cast<const __half2*>(&qa[k].z);
        const __half2 e11 = *reinterpret_cast<const __half2*>(&qa[k].w);

        __half2 wl2 = __float2half2_rn(wlat);
        __half2 c0h = __hfma2(__hsub2(e10, e00), wl2, e00);
        __half2 c1h = __hfma2(__hsub2(e11, e01), wl2, e01);

        float2 c0 = __half22float2(c0h);
        float2 c1 = __half22float2(c1h);

        res[2 * k + 0] = fmaf(c1.x - c0.x, wlon, c0.x) * SCALE_DOWN;
        res[2 * k + 1] = fmaf(c1.y - c0.y, wlon, c0.y) * SCALE_DOWN;
    }

    // Each lane stores its own 16B of the 32B output row (coalesced).
    reinterpret_cast<float4*>(out)[(size_t)pt * 2 + h] =
        make_float4(res[0], res[1], res[2], res[3]);
}

extern "C" void kernel_launch(void* const* d_in, const int* in_sizes, int n_in,
                              void* d_out, int out_size)
{
    const float* x   = (const float*)d_in[0];
    const float* emb = (const float*)d_in[1];
    float*       out = (float*)d_out;

    int B = in_sizes[0] / 2;
    const int T = 256;

    build_recs<<<(4 * NREC + T - 1) / T, T>>>(emb);

    long long nthreads = 2LL * B;
    interp_kernel<<<(int)((nthreads + T - 1) / T), T>>>(x, out, B);
}

// round 17
// speedup vs baseline: 1.4091x; 1.0718x over previous
#include <cuda_runtime.h>
#include <cuda_fp16.h>
#include <cuda_bf16.h>

// NGP geodesic-weighted multi-level grid interpolation — 64B fused record,
// lane-pair split (R15/R16) + f32x2 packed math + streaming cache hints.
//
// Validated structure: rec[cell0] = 4 fp16 corner-quads (64B, L2-resident,
// level-i cell = cell0 >> i); thread = (point, half); one LDG.256 per lane,
// lane pairs share the 128B line (merged wavefront); fp16 lat-lerp.
// This round (issue-bound per R16 profile): the two levels' weight math and
// the final lon-lerp run on sm_103a packed f32x2 pipes (fma.rn.f32x2 /
// mul.rn.f32x2 -> FFMA2 in SASS), and output/x use .cs streaming hints so
// the 64MB output stream stops evicting the record table from L2.

#define TABLE_SIZE (721 * 1441)
#define NREC 261008   // >= 180*1440 + 360 + margin (reachable level-0 cells)

#define BM0 (-90.25f)
#define BM1 (-0.25f)
#define BX0 (90.25f)
#define BX1 (360.25f)
#define RAD 0.017453292519943295f
#define SCALE_UP   8192.0f          // 2^13, exact
#define SCALE_DOWN (1.0f / 8192.0f) // exact

// Per-level constants: K = gs*RAD/2; sd = K - K^3/6; 1/sd; sd^2; 1/gs.
__device__ __constant__ float KH[4]     = {0.0087266462f, 0.0174532925f,
                                           0.0349065850f, 0.0698131701f};
__device__ __constant__ float INV_SD[4] = {114.593013f, 57.2986883f,
                                           28.6537073f, 14.3355896f};
__device__ __constant__ float SD2[4]    = {7.6152418e-5f, 3.0458649e-4f,
                                           1.2179748e-3f, 4.8659614e-3f};
__device__ __constant__ float INV_GS[4] = {1.0f, 0.5f, 0.25f, 0.125f};

// rec[cell0] = 4 x fp16-quad {e00x,e00y,e01x,e01y,e10x,e10y,e11x,e11y}.
__device__ __align__(64) uint4 g_recs[4 * NREC];   // 16.7 MB

// ---- packed f32x2 helpers (sm_103a) ----
typedef unsigned long long f32x2;
__device__ __forceinline__ f32x2 pk(float a, float b)
{ f32x2 r; asm("mov.b64 %0,{%1,%2};" : "=l"(r) : "f"(a), "f"(b)); return r; }
__device__ __forceinline__ void upk(f32x2 v, float& a, float& b)
{ asm("mov.b64 {%0,%1},%2;" : "=f"(a), "=f"(b) : "l"(v)); }
__device__ __forceinline__ f32x2 fma2p(f32x2 a, f32x2 b, f32x2 c)
{ f32x2 d; asm("fma.rn.f32x2 %0,%1,%2,%3;" : "=l"(d) : "l"(a), "l"(b), "l"(c)); return d; }
__device__ __forceinline__ f32x2 mul2p(f32x2 a, f32x2 b)
{ f32x2 d; asm("mul.rn.f32x2 %0,%1,%2;" : "=l"(d) : "l"(a), "l"(b)); return d; }

// 4 threads per record, one per level -> fully coalesced 16B stores.
__global__ __launch_bounds__(256)
void build_recs(const float* __restrict__ emb)
{
    int t = blockIdx.x * blockDim.x + threadIdx.x;
    if (t >= 4 * NREC) return;
    int rec = t >> 2;
    int lvl = t & 3;

    int ib0 = rec / 1440;
    int ib1 = rec - ib0 * 1440;

    int W = 1440 >> lvl;
    int j = (ib0 >> lvl) * W + (ib1 >> lvl);

    const float2* tab = reinterpret_cast<const float2*>(emb) + lvl * TABLE_SIZE;
    float2 a = __ldg(tab + j);         // e00
    float2 b = __ldg(tab + j + 1);     // e01
    float2 c = __ldg(tab + j + W);     // e10
    float2 d = __ldg(tab + j + W + 1); // e11

    __half2 h0 = __floats2half2_rn(a.x * SCALE_UP, a.y * SCALE_UP);
    __half2 h1 = __floats2half2_rn(b.x * SCALE_UP, b.y * SCALE_UP);
    __half2 h2 = __floats2half2_rn(c.x * SCALE_UP, c.y * SCALE_UP);
    __half2 h3 = __floats2half2_rn(d.x * SCALE_UP, d.y * SCALE_UP);

    uint4 q;
    q.x = *reinterpret_cast<unsigned*>(&h0);
    q.y = *reinterpret_cast<unsigned*>(&h1);
    q.z = *reinterpret_cast<unsigned*>(&h2);
    q.w = *reinterpret_cast<unsigned*>(&h3);
    g_recs[t] = q;
}

// 256-bit global load (Blackwell LDG.E.256); bits only, via f32 regs.
__device__ __forceinline__ void ldg256(const uint4* p, uint4& a, uint4& b)
{
    float ax, ay, az, aw, bx, by, bz, bw;
    asm volatile("ld.global.v8.f32 {%0,%1,%2,%3,%4,%5,%6,%7}, [%8];"
                 : "=f"(ax), "=f"(ay), "=f"(az), "=f"(aw),
                   "=f"(bx), "=f"(by), "=f"(bz), "=f"(bw)
                 : "l"(p));
    a.x = __float_as_uint(ax); a.y = __float_as_uint(ay);
    a.z = __float_as_uint(az); a.w = __float_as_uint(aw);
    b.x = __float_as_uint(bx); b.y = __float_as_uint(by);
    b.z = __float_as_uint(bz); b.w = __float_as_uint(bw);
}

__global__ __launch_bounds__(256, 6)
void interp_kernel(const float* __restrict__ x,
                   float* __restrict__ out,
                   int B)
{
    int t  = blockIdx.x * blockDim.x + threadIdx.x;
    int pt = t >> 1;            // point index
    int h  = t & 1;             // half: levels {2h, 2h+1}
    if (pt >= B) return;

    // Streamed, read-once point load.
    float2 p;
    asm("ld.global.cs.v2.f32 {%0,%1},[%2];"
        : "=f"(p.x), "=f"(p.y)
        : "l"(reinterpret_cast<const float2*>(x) + pt));
    float lat = p.x, lon = p.y;
    float clat = fminf(fmaxf(lat, BM0), BX0);
    float clon = fminf(fmaxf(lon, BM1), BX1);

    // Level-0 cell; coarser levels by exact pow2 shift.
    int ib0 = __float2int_rd(clat - BM0);
    int ib1 = __float2int_rd(clon - BM1);

    // ONE LDG.256: this lane's 32B half of the 64B record (lane pairs share
    // the 128B line -> merged wavefront).
    const uint4* rec = g_recs + ((size_t)(ib0 * 1440 + ib1) * 4 + h * 2);
    uint4 qa[2];
    ldg256(rec, qa[0], qa[1]);

    const int lA = 2 * h, lB = 2 * h + 1;

    // Per-lane shared terms.
    float latb = lat - BM0;                 // wlat uses UNCLIPPED lat
    float lonr = (lon - BM1) * (RAD * 0.5f);

    // c^2 = cos^2(clat*RAD) via degree-8 even Taylor of cos(2theta), once.
    float th = clat * RAD;
    float w  = 4.0f * th * th;
    float cv = fmaf(w, fmaf(w, fmaf(w, fmaf(w, 1.0f / 40320.0f,
                                           -1.0f / 720.0f),
                                    1.0f / 24.0f),
                            -0.5f), 1.0f);
    float c2_6 = fmaf(0.5f, cv, 0.5f) * (1.0f / 6.0f);

    // ---- packed weight math for both levels ----
    float fniA = (float)(-(ib0 >> lA)), fniB = (float)(-(ib0 >> lB));
    float fipA = (float)((ib1 >> lA) + 1), fipB = (float)((ib1 >> lB) + 1);

    f32x2 latb2  = pk(latb, latb);
    f32x2 nlonr2 = pk(-lonr, -lonr);
    f32x2 one2   = pk(1.0f, 1.0f);

    // wlat = latb/gs - fi0
    f32x2 wlat2 = fma2p(latb2, pk(INV_GS[lA], INV_GS[lB]), pk(fniA, fniB));
    // zn = K*(fi1+1) - lonr ; sn = zn*(1 - zn^2/6)
    f32x2 zn2   = fma2p(pk(KH[lA], KH[lB]), pk(fipA, fipB), nlonr2);
    f32x2 znsq2 = mul2p(zn2, zn2);
    f32x2 sn2   = mul2p(zn2, fma2p(znsq2, pk(-1.0f / 6.0f, -1.0f / 6.0f), one2));
    // wlon = sn/sd * (1 + c2*(zn^2 - sd^2)/6)
    float baseA = fmaf(-c2_6, SD2[lA], 1.0f);
    float baseB = fmaf(-c2_6, SD2[lB], 1.0f);
    f32x2 corr2 = fma2p(pk(c2_6, c2_6), znsq2, pk(baseA, baseB));
    f32x2 wlon2 = mul2p(mul2p(sn2, pk(INV_SD[lA], INV_SD[lB])), corr2);
    // 1 - wlon
    f32x2 omw2  = fma2p(wlon2, pk(-1.0f, -1.0f), one2);

    float wlA_, wlB_, woA, woB, omA, omB;
    upk(wlat2, wlA_, wlB_);
    upk(wlon2, woA, woB);
    upk(omw2,  omA, omB);
    const float wlat_s[2] = {wlA_, wlB_};
    const float wlon_s[2] = {woA, woB};
    const float omw_s[2]  = {omA, omB};

    f32x2 sd2p = pk(SCALE_DOWN, SCALE_DOWN);

    float res[4];
#pragma unroll
    for (int k = 0; k < 2; k++) {
        // fp16 lat-lerp on stored half2 corners.
        const __half2 e00 = *reinterpret_cast<const __half2*>(&qa[k].x);
        const __half2 e01 = *reinterpret_cast<const __half2*>(&qa[k].y);
        const __half2 e10 = *reinterpret_cast<const __half2*>(&qa[k].z);
        const __half2 e11 = *reinterpret_cast<const __half2*>(&qa[k].w);

        __half2 wl2 = __float2half2_rn(wlat_s[k]);
        __half2 c0h = __hfma2(__hsub2(e10, e00), wl2, e00);
        __half2 c1h = __hfma2(__hsub2(e11, e01), wl2, e01);

        float2 c0 = __half22float2(c0h);
        float2 c1 = __half22float2(c1h);

        // res = (c0*(1-wlon) + c1*wlon) * 2^-13, packed.
        f32x2 c02 = pk(c0.x, c0.y);
        f32x2 c12 = pk(c1.x, c1.y);
        f32x2 r2  = mul2p(c02, pk(omw_s[k], omw_s[k]));
        r2 = fma2p(c12, pk(wlon_s[k], wlon_s[k]), r2);
        r2 = mul2p(r2, sd2p);
        upk(r2, res[2 * k + 0], res[2 * k + 1]);
    }

    // Streaming store: each lane's own 16B of the 32B output row.
    float4* o = reinterpret_cast<float4*>(out) + ((size_t)pt * 2 + h);
    asm volatile("st.global.cs.v4.f32 [%0],{%1,%2,%3,%4};"
                 :: "l"(o), "f"(res[0]), "f"(res[1]), "f"(res[2]), "f"(res[3]));
}

extern "C" void kernel_launch(void* const* d_in, const int* in_sizes, int n_in,
                              void* d_out, int out_size)
{
    const float* x   = (const float*)d_in[0];
    const float* emb = (const float*)d_in[1];
    float*       out = (float*)d_out;

    int B = in_sizes[0] / 2;
    const int T = 256;

    build_recs<<<(4 * NREC + T - 1) / T, T>>>(emb);

    long long nthreads = 2LL * B;
    interp_kernel<<<(int)((nthreads + T - 1) / T), T>>>(x, out, B);
}